// round 3
// baseline (speedup 1.0000x reference)
#include <cuda_runtime.h>
#include <float.h>
#include <math.h>

// Problem constants
#define Bn 8
#define In 32
#define On 32
#define Dn 8
#define Hn 14
#define Wn 14
#define Kn 9
#define WK (Wn*Kn)            // 126
#define NT 256
#define SUBSET 26             // ceil(0.8 * 32)
#define D_STRIDE (Hn*WK)      // 1764 floats between d-planes of one capsule
#define CAP_STRIDE (Dn*D_STRIDE) // 14112 floats between capsules

__global__ __launch_bounds__(NT)
void conv_subset_routing_kernel(const float* __restrict__ x,
                                float* __restrict__ out) {
    // smem state for one (b, o, h) row of 14 sites
    __shared__ float xs[Dn][WK];        // staged raw data for one input cap
    __shared__ float nrm[WK];           // per-(w,k) norm over D
    __shared__ float x1s[In * Dn * Wn]; // x1[i][d][w]
    __shared__ float n1s[In * Wn];      // ||x1_i|| per site
    __shared__ float loss[In * Wn];
    __shared__ float vsh[Dn * Wn];      // consensus v
    __shared__ float cand[In * Wn];
    __shared__ float thr[Wn];

    const int tid = threadIdx.x;
    const int bid = blockIdx.x;
    const int h = bid % Hn;
    const int o = (bid / Hn) % On;
    const int b = bid / (Hn * On);

    const int dd = tid / Wn;   // role (d, w) for tid < 112
    const int ww = tid % Wn;

    // base float offset of (b, i=0, o, d=0, h, w=0, k=0)
    const size_t bo_base = (size_t)(b * In * On + o) * CAP_STRIDE + (size_t)h * WK;

    // ---- stage 1: per input cap, weighted-average over kernel positions ----
    for (int i = 0; i < In; ++i) {
        const size_t ibase = bo_base + (size_t)i * On * CAP_STRIDE;

        // coalesced streaming load of D x 126 floats (as float2, 8B aligned)
        for (int it = tid; it < Dn * (WK / 2); it += NT) {
            const int d  = it / (WK / 2);
            const int j2 = it - d * (WK / 2);
            const float2 v2 = __ldcs(reinterpret_cast<const float2*>(
                x + ibase + (size_t)d * D_STRIDE + 2 * j2));
            xs[d][2 * j2]     = v2.x;
            xs[d][2 * j2 + 1] = v2.y;
        }
        __syncthreads();

        // per-(w,k) norm over D
        if (tid < WK) {
            float s = 0.f;
            #pragma unroll
            for (int d = 0; d < Dn; ++d) { const float v = xs[d][tid]; s += v * v; }
            nrm[tid] = sqrtf(s);
        }
        __syncthreads();

        // x1[i][d][w] = sum_k n_k * x[d][w,k] / sum_k n_k
        if (tid < Dn * Wn) {
            const int jb = ww * Kn;
            float den = 0.f, num = 0.f;
            #pragma unroll
            for (int k = 0; k < Kn; ++k) {
                const float nk = nrm[jb + k];
                den += nk;
                num += nk * xs[dd][jb + k];
            }
            x1s[i * (Dn * Wn) + tid] = num / den;
        }
        __syncthreads();   // protect xs before next cap's load
    }

    // ---- n1[i][w] = ||x1_i|| ----
    for (int it = tid; it < In * Wn; it += NT) {
        const int i = it / Wn, w = it - i * Wn;
        float s = 0.f;
        #pragma unroll
        for (int d = 0; d < Dn; ++d) {
            const float v = x1s[i * (Dn * Wn) + d * Wn + w];
            s += v * v;
        }
        n1s[it] = sqrtf(s);
    }
    __syncthreads();

    // ---- consensus v[d][w] ----
    if (tid < Dn * Wn) {
        float num = 0.f, den = 0.f;
        #pragma unroll
        for (int i = 0; i < In; ++i) {
            const float n = n1s[i * Wn + ww];
            num += n * x1s[i * (Dn * Wn) + tid];
            den += n;
        }
        vsh[tid] = num / den;
    }
    __syncthreads();

    // ---- losses[i][w] = -v . x1_i ----
    for (int it = tid; it < In * Wn; it += NT) {
        const int i = it / Wn, w = it - i * Wn;
        float s = 0.f;
        #pragma unroll
        for (int d = 0; d < Dn; ++d)
            s += vsh[d * Wn + w] * x1s[i * (Dn * Wn) + d * Wn + w];
        loss[it] = -s;
    }
    __syncthreads();

    // ---- kth smallest via rank counting:
    //      thr = min{ l_j : #{m : l_m <= l_j} >= SUBSET }  ==  sorted[SUBSET-1]
    for (int it = tid; it < In * Wn; it += NT) {
        const int j = it / Wn, w = it - j * Wn;
        const float lj = loss[j * Wn + w];
        int c = 0;
        #pragma unroll
        for (int m = 0; m < In; ++m)
            c += (loss[m * Wn + w] <= lj) ? 1 : 0;
        cand[it] = (c >= SUBSET) ? lj : FLT_MAX;
    }
    __syncthreads();

    if (tid < Wn) {
        float t = FLT_MAX;
        #pragma unroll
        for (int j = 0; j < In; ++j) t = fminf(t, cand[j * Wn + tid]);
        thr[tid] = t;
    }
    __syncthreads();

    // ---- final weighted average over chosen subset ----
    if (tid < Dn * Wn) {
        const float tw = thr[ww];
        float num = 0.f, den = 0.f;
        #pragma unroll
        for (int i = 0; i < In; ++i) {
            if (loss[i * Wn + ww] <= tw) {
                const float n = n1s[i * Wn + ww];
                num += n * x1s[i * (Dn * Wn) + tid];
                den += n;
            }
        }
        out[((size_t)((b * On + o) * Dn + dd) * Hn + h) * Wn + ww] = num / den;
    }
}

extern "C" void kernel_launch(void* const* d_in, const int* in_sizes, int n_in,
                              void* d_out, int out_size) {
    const float* x = (const float*)d_in[0];
    float* out = (float*)d_out;
    conv_subset_routing_kernel<<<Bn * On * Hn, NT>>>(x, out);
}

// round 7
// speedup vs baseline: 1.6900x; 1.6900x over previous
#include <cuda_runtime.h>
#include <float.h>
#include <math.h>

// Problem constants
#define Bn 8
#define In 32
#define On 32
#define Dn 8
#define Hn 14
#define Wn 14
#define Kn 9
#define WK (Wn*Kn)               // 126
#define NT 256
#define NGROUP 4
#define GSZ 64                   // threads per group
#define CAPS_PER_GROUP (In/NGROUP)  // 8
#define SUBSET 26                // ceil(0.8 * 32)
#define D_STRIDE (Hn*WK)         // 1764 floats between d-planes of one capsule
#define CAP_STRIDE (Dn*D_STRIDE) // 14112 floats between capsules
#define DW (Dn*Wn)               // 112
#define NF2 (Dn*(WK/2))          // 504 float2 per cap
#define NPREF 8                  // ceil(504/64) prefetch regs per thread

__device__ __forceinline__ void group_bar(int id) {
    asm volatile("bar.sync %0, %1;" :: "r"(id), "r"(GSZ) : "memory");
}

__global__ __launch_bounds__(NT, 5)
void conv_subset_routing_kernel(const float* __restrict__ x,
                                float* __restrict__ out) {
    // per-group staging buffers
    __shared__ float xs[NGROUP][Dn][WK];   // raw data for the group's current cap
    __shared__ float nrm[NGROUP][WK];      // per-(w,k) norm over D
    // CTA-wide state
    __shared__ float x1s[In * DW];         // x1[i][d][w]
    __shared__ float n1s[In * Wn];         // ||x1_i|| per site
    __shared__ float loss[In * Wn];
    __shared__ float vsh[DW];              // consensus v
    __shared__ float cand[In * Wn];
    __shared__ float thr[Wn];

    const int tid = threadIdx.x;
    const int bid = blockIdx.x;
    const int h = bid % Hn;
    const int o = (bid / Hn) % On;
    const int b = bid / (Hn * On);

    const int g  = tid >> 6;      // group 0..3
    const int lt = tid & 63;      // lane within group

    const int dd = tid / Wn;      // role (d, w) for tid < 112 (stages 2+)
    const int ww = tid % Wn;

    // base float offset of (b, i=0, o, d=0, h, w=0, k=0)
    const size_t bo_base = (size_t)(b * In * On + o) * CAP_STRIDE + (size_t)h * WK;

    float* const xsg  = &xs[g][0][0];
    float* const nrmg = nrm[g];
    const int barid = g + 1;

    // per-lane fixed load roles: it = lt + r*64 -> (d, j2)
    int ld_off[NPREF];            // float offset of this lane's r-th float2
    bool ld_ok[NPREF];
    #pragma unroll
    for (int r = 0; r < NPREF; ++r) {
        const int it = lt + r * GSZ;
        ld_ok[r] = (it < NF2);
        const int d  = it / (WK / 2);
        const int j2 = it - d * (WK / 2);
        ld_off[r] = d * D_STRIDE + 2 * j2;
    }
    int st_off[NPREF];            // smem float offset for the same element
    #pragma unroll
    for (int r = 0; r < NPREF; ++r) {
        const int it = lt + r * GSZ;
        const int d  = it / (WK / 2);
        const int j2 = it - d * (WK / 2);
        st_off[r] = d * WK + 2 * j2;
    }

    const float* gbase = x + bo_base + (size_t)(g * CAPS_PER_GROUP) * (On * CAP_STRIDE);
    const size_t cap_step = (size_t)On * CAP_STRIDE;

    // ---- stage 1: per input cap, weighted-average over kernel positions ----
    // each 64-thread group handles 8 caps; loads double-buffered in registers
    float2 rv[NPREF];
    #pragma unroll
    for (int r = 0; r < NPREF; ++r)
        if (ld_ok[r])
            rv[r] = __ldcs(reinterpret_cast<const float2*>(gbase + ld_off[r]));

    for (int ic = 0; ic < CAPS_PER_GROUP; ++ic) {
        const int i = g * CAPS_PER_GROUP + ic;

        // xs free (prev x1 compute done) -> dump registers to smem
        group_bar(barid);
        #pragma unroll
        for (int r = 0; r < NPREF; ++r)
            if (ld_ok[r])
                *reinterpret_cast<float2*>(&xsg[st_off[r]]) = rv[r];

        // issue next cap's loads; they fly during the compute below
        if (ic + 1 < CAPS_PER_GROUP) {
            const float* nbase = gbase + (size_t)(ic + 1) * cap_step;
            #pragma unroll
            for (int r = 0; r < NPREF; ++r)
                if (ld_ok[r])
                    rv[r] = __ldcs(reinterpret_cast<const float2*>(nbase + ld_off[r]));
        }
        group_bar(barid);   // xs populated

        // per-(w,k) norm over D (126 roles over 64 lanes)
        #pragma unroll
        for (int r = 0; r < 2; ++r) {
            const int j = lt + r * GSZ;
            if (j < WK) {
                float s = 0.f;
                #pragma unroll
                for (int d = 0; d < Dn; ++d) {
                    const float v = xsg[d * WK + j];
                    s += v * v;
                }
                nrmg[j] = sqrtf(s);
            }
        }
        group_bar(barid);

        // x1[i][d][w] = sum_k n_k * x[d][w,k] / sum_k n_k  (112 roles)
        #pragma unroll
        for (int r = 0; r < 2; ++r) {
            const int t = lt + r * GSZ;
            if (t < DW) {
                const int d = t / Wn;
                const int w = t - d * Wn;
                const int jb = w * Kn;
                float den = 0.f, num = 0.f;
                #pragma unroll
                for (int k = 0; k < Kn; ++k) {
                    const float nk = nrmg[jb + k];
                    den += nk;
                    num += nk * xsg[d * WK + jb + k];
                }
                x1s[i * DW + t] = num / den;
            }
        }
    }
    __syncthreads();        // all groups' x1 complete

    // ---- n1[i][w] = ||x1_i|| ----
    for (int it = tid; it < In * Wn; it += NT) {
        const int i = it / Wn, w = it - i * Wn;
        const float* p = &x1s[i * DW + w];
        float s = 0.f;
        #pragma unroll
        for (int d = 0; d < Dn; ++d) {
            const float v = p[d * Wn];
            s += v * v;
        }
        n1s[it] = sqrtf(s);
    }
    __syncthreads();

    // ---- consensus v[d][w] ----
    if (tid < DW) {
        float num = 0.f, den = 0.f;
        const float* p = &x1s[tid];
        const float* q = &n1s[ww];
        #pragma unroll
        for (int i = 0; i < In; ++i) {
            const float n = q[i * Wn];
            num += n * p[i * DW];
            den += n;
        }
        vsh[tid] = num / den;
    }
    __syncthreads();

    // ---- losses[i][w] = -v . x1_i ----
    for (int it = tid; it < In * Wn; it += NT) {
        const int i = it / Wn, w = it - i * Wn;
        const float* p = &x1s[i * DW + w];
        float s = 0.f;
        #pragma unroll
        for (int d = 0; d < Dn; ++d)
            s += vsh[d * Wn + w] * p[d * Wn];
        loss[it] = -s;
    }
    __syncthreads();

    // ---- kth smallest via rank counting:
    //      thr = min{ l_j : #{m : l_m <= l_j} >= SUBSET }  ==  sorted[SUBSET-1]
    for (int it = tid; it < In * Wn; it += NT) {
        const int j = it / Wn, w = it - j * Wn;
        const float lj = loss[j * Wn + w];
        int c = 0;
        #pragma unroll
        for (int m = 0; m < In; ++m)
            c += (loss[m * Wn + w] <= lj) ? 1 : 0;
        cand[it] = (c >= SUBSET) ? lj : FLT_MAX;
    }
    __syncthreads();

    if (tid < Wn) {
        float t = FLT_MAX;
        #pragma unroll
        for (int j = 0; j < In; ++j) t = fminf(t, cand[j * Wn + tid]);
        thr[tid] = t;
    }
    __syncthreads();

    // ---- final weighted average over chosen subset ----
    if (tid < DW) {
        const float tw = thr[ww];
        float num = 0.f, den = 0.f;
        const float* p = &x1s[tid];
        #pragma unroll
        for (int i = 0; i < In; ++i) {
            if (loss[i * Wn + ww] <= tw) {
                const float n = n1s[i * Wn + ww];
                num += n * p[i * DW];
                den += n;
            }
        }
        out[((size_t)((b * On + o) * Dn + dd) * Hn + h) * Wn + ww] = num / den;
    }
}

extern "C" void kernel_launch(void* const* d_in, const int* in_sizes, int n_in,
                              void* d_out, int out_size) {
    const float* x = (const float*)d_in[0];
    float* out = (float*)d_out;
    conv_subset_routing_kernel<<<Bn * On * Hn, NT>>>(x, out);
}

// round 9
// speedup vs baseline: 1.8478x; 1.0934x over previous
#include <cuda_runtime.h>
#include <float.h>
#include <math.h>

// Problem constants
#define Bn 8
#define In 32
#define On 32
#define Dn 8
#define Hn 14
#define Wn 14
#define Kn 9
#define WK (Wn*Kn)               // 126
#define WK2 (WK/2)               // 63 float2 columns
#define NT 256
#define NGROUP 4
#define GSZ 64                   // threads per group
#define CAPS_PER_GROUP (In/NGROUP)  // 8
#define SUBSET 26                // ceil(0.8 * 32)
#define D_STRIDE (Hn*WK)         // 1764 floats between d-planes of one capsule
#define CAP_STRIDE (Dn*D_STRIDE) // 14112 floats between capsules
#define DW (Dn*Wn)               // 112

__device__ __forceinline__ void group_bar(int id) {
    asm volatile("bar.sync %0, %1;" :: "r"(id), "r"(GSZ) : "memory");
}

// Stage-1 scratch (per-group) and stage-2+ scratch are live in disjoint
// phases -> overlay them to cut smem from 38.4KB to 32.5KB (6 CTAs/SM).
struct Stage1 {
    float nx[NGROUP][Dn][WK];    // premultiplied n_j * x[d][j] for current cap
    float nsm[NGROUP][WK];       // per-(w,k) norm over D
};
struct Stage2 {
    float n1s[In * Wn];          // ||x1_i|| per site
    float loss[In * Wn];
    float cand[In * Wn];
    float vsh[DW];               // consensus v
    float thr[Wn];
};

__global__ __launch_bounds__(NT, 6)
void conv_subset_routing_kernel(const float* __restrict__ x,
                                float* __restrict__ out) {
    __shared__ union { Stage1 s1; Stage2 s2; } u;
    __shared__ float x1s[In * DW];         // x1[i][d][w] (persists all stages)

    const int tid = threadIdx.x;
    const int bid = blockIdx.x;
    const int h = bid % Hn;
    const int o = (bid / Hn) % On;
    const int b = bid / (Hn * On);

    const int g  = tid >> 6;      // group 0..3
    const int lt = tid & 63;      // lane within group

    const int dd = tid / Wn;      // role (d, w) for tid < 112 (stages 2+)
    const int ww = tid % Wn;

    // base float offset of (b, i=0, o, d=0, h, w=0, k=0)
    const size_t bo_base = (size_t)(b * In * On + o) * CAP_STRIDE + (size_t)h * WK;

    float* const nxg = &u.s1.nx[g][0][0];
    float* const nsg = u.s1.nsm[g];
    const int barid = g + 1;
    const bool colth = (lt < WK2);          // 63 column-owner threads per group

    const float* gbase = x + bo_base + (size_t)(g * CAPS_PER_GROUP) * (On * CAP_STRIDE)
                           + 2 * lt;        // this thread's column base
    const size_t cap_step = (size_t)On * CAP_STRIDE;

    // ---- stage 1: per input cap, weighted-average over kernel positions ----
    // each 64-thread group handles 8 caps; loads double-buffered in registers;
    // D-norm computed purely in registers (no smem round-trip).
    float2 rv[Dn];
    if (colth) {
        #pragma unroll
        for (int d = 0; d < Dn; ++d)
            rv[d] = __ldcs(reinterpret_cast<const float2*>(gbase + d * D_STRIDE));
    }

    for (int ic = 0; ic < CAPS_PER_GROUP; ++ic) {
        const int i = g * CAPS_PER_GROUP + ic;

        // register-only: norms for this thread's two columns, premultiply
        float n0 = 0.f, n1 = 0.f;
        if (colth) {
            #pragma unroll
            for (int d = 0; d < Dn; ++d) {
                n0 += rv[d].x * rv[d].x;
                n1 += rv[d].y * rv[d].y;
            }
            n0 = sqrtf(n0);
            n1 = sqrtf(n1);
            #pragma unroll
            for (int d = 0; d < Dn; ++d) {
                rv[d].x *= n0;
                rv[d].y *= n1;
            }
        }

        group_bar(barid);   // prev x1 compute done -> nx/nsm free
        if (colth) {
            #pragma unroll
            for (int d = 0; d < Dn; ++d)
                *reinterpret_cast<float2*>(&nxg[d * WK + 2 * lt]) = rv[d];
            *reinterpret_cast<float2*>(&nsg[2 * lt]) = make_float2(n0, n1);

            // issue next cap's loads; they fly during the x1 compute below
            if (ic + 1 < CAPS_PER_GROUP) {
                const float* nb = gbase + (size_t)(ic + 1) * cap_step;
                #pragma unroll
                for (int d = 0; d < Dn; ++d)
                    rv[d] = __ldcs(reinterpret_cast<const float2*>(nb + d * D_STRIDE));
            }
        }
        group_bar(barid);   // nx/nsm populated

        // x1[i][d][w] = sum_k nx[d][w*9+k] / sum_k n[w*9+k]  (112 roles)
        float* const x1row = &x1s[i * DW];
        #pragma unroll
        for (int r = 0; r < 2; ++r) {
            const int t = lt + r * GSZ;
            if (t < DW) {
                const int d = t / Wn;
                const int w = t - d * Wn;
                const int jb = w * Kn;
                float den = 0.f, num = 0.f;
                #pragma unroll
                for (int k = 0; k < Kn; ++k) {
                    den += nsg[jb + k];
                    num += nxg[d * WK + jb + k];
                }
                x1row[t] = num / den;
            }
        }
    }
    __syncthreads();        // all groups' x1 complete; stage-1 scratch dead

    // ---- n1[i][w] = ||x1_i|| ----
    for (int it = tid; it < In * Wn; it += NT) {
        const int i = it / Wn, w = it - i * Wn;
        const float* p = &x1s[i * DW + w];
        float s = 0.f;
        #pragma unroll
        for (int d = 0; d < Dn; ++d) {
            const float v = p[d * Wn];
            s += v * v;
        }
        u.s2.n1s[it] = sqrtf(s);
    }
    __syncthreads();

    // ---- consensus v[d][w] ----
    if (tid < DW) {
        float num = 0.f, den = 0.f;
        const float* p = &x1s[tid];
        const float* q = &u.s2.n1s[ww];
        #pragma unroll
        for (int i = 0; i < In; ++i) {
            const float n = q[i * Wn];
            num += n * p[i * DW];
            den += n;
        }
        u.s2.vsh[tid] = num / den;
    }
    __syncthreads();

    // ---- losses[i][w] = -v . x1_i ----
    for (int it = tid; it < In * Wn; it += NT) {
        const int i = it / Wn, w = it - i * Wn;
        const float* p = &x1s[i * DW + w];
        float s = 0.f;
        #pragma unroll
        for (int d = 0; d < Dn; ++d)
            s += u.s2.vsh[d * Wn + w] * p[d * Wn];
        u.s2.loss[it] = -s;
    }
    __syncthreads();

    // ---- kth smallest via rank counting:
    //      thr = min{ l_j : #{m : l_m <= l_j} >= SUBSET }  ==  sorted[SUBSET-1]
    for (int it = tid; it < In * Wn; it += NT) {
        const int j = it / Wn, w = it - j * Wn;
        const float lj = u.s2.loss[j * Wn + w];
        int c = 0;
        #pragma unroll
        for (int m = 0; m < In; ++m)
            c += (u.s2.loss[m * Wn + w] <= lj) ? 1 : 0;
        u.s2.cand[it] = (c >= SUBSET) ? lj : FLT_MAX;
    }
    __syncthreads();

    if (tid < Wn) {
        float t = FLT_MAX;
        #pragma unroll
        for (int j = 0; j < In; ++j) t = fminf(t, u.s2.cand[j * Wn + tid]);
        u.s2.thr[tid] = t;
    }
    __syncthreads();

    // ---- final weighted average over chosen subset ----
    if (tid < DW) {
        const float tw = u.s2.thr[ww];
        float num = 0.f, den = 0.f;
        const float* p = &x1s[tid];
        #pragma unroll
        for (int i = 0; i < In; ++i) {
            if (u.s2.loss[i * Wn + ww] <= tw) {
                const float n = u.s2.n1s[i * Wn + ww];
                num += n * p[i * DW];
                den += n;
            }
        }
        out[((size_t)((b * On + o) * Dn + dd) * Hn + h) * Wn + ww] = num / den;
    }
}

extern "C" void kernel_launch(void* const* d_in, const int* in_sizes, int n_in,
                              void* d_out, int out_size) {
    const float* x = (const float*)d_in[0];
    float* out = (float*)d_out;
    conv_subset_routing_kernel<<<Bn * On * Hn, NT>>>(x, out);
}